// round 3
// baseline (speedup 1.0000x reference)
#include <cuda_runtime.h>

// Problem constants (fixed shapes from reference setup_inputs; stride=1, reps=1)
#define SLOTS   65536
#define SMASK   (SLOTS - 1)
#define SQ      (SLOTS / 4)      // quads per row
#define BATCH   64
#define BPC     8                // batches per CTA
#define TPB     256              // threads per block; slot tile = TPB*4 = 1024

// ---------------------------------------------------------------------------
// Kernel 1: t = 0..7  (shifts 1,2,4,8,16,32,64,128). Writes out.
//   t=0,1 are lane swizzles of aligned quads A=x[s2..s2+3], B=x[s2+4..s2+7];
//   t=2 operand == B. Loads per batch: A, B, and shifts {8,16,32,64,128} -> 7.
//   dv regs: 8 float4 = 32 -> fits 3 CTAs/SM.
// ---------------------------------------------------------------------------
__global__ __launch_bounds__(TPB, 3)
void fhe_bsgs_lo(const float* __restrict__ x,
                 const float* __restrict__ diag,
                 float* __restrict__ out)
{
    const int s  = blockIdx.x * (TPB * 4) + threadIdx.x * 4;
    const int s2 = s ^ 32768;
    const int b0 = blockIdx.y * BPC;

    const float4* __restrict__ x4 = reinterpret_cast<const float4*>(x);
    const float4* __restrict__ d4 = reinterpret_cast<const float4*>(diag);
    float4* __restrict__ o4 = reinterpret_cast<float4*>(out);

    const unsigned q2 = (unsigned)s2 >> 2;

    float4 dv[8];
    #pragma unroll
    for (int t = 0; t < 8; t++)
        dv[t] = d4[t * SQ + q2];

    const unsigned qA = q2;
    const unsigned qB = ((unsigned)(s2 + 4)   & SMASK) >> 2;
    const unsigned q3 = ((unsigned)(s2 + 8)   & SMASK) >> 2;
    const unsigned q4 = ((unsigned)(s2 + 16)  & SMASK) >> 2;
    const unsigned q5 = ((unsigned)(s2 + 32)  & SMASK) >> 2;
    const unsigned q6 = ((unsigned)(s2 + 64)  & SMASK) >> 2;
    const unsigned q7 = ((unsigned)(s2 + 128) & SMASK) >> 2;
    const unsigned oq = (unsigned)s >> 2;

    #pragma unroll
    for (int i = 0; i < BPC; i++) {
        const int b = b0 + i;
        const float4* __restrict__ xr = x4 + (size_t)b * SQ;

        const float4 A  = xr[qA];
        const float4 Bv = xr[qB];
        const float4 X3 = xr[q3];
        const float4 X4 = xr[q4];
        const float4 X5 = xr[q5];
        const float4 X6 = xr[q6];
        const float4 X7 = xr[q7];

        float4 acc;
        // t=0: (A.y, A.z, A.w, B.x)
        acc.x = A.y  * dv[0].x;
        acc.y = A.z  * dv[0].y;
        acc.z = A.w  * dv[0].z;
        acc.w = Bv.x * dv[0].w;
        // t=1: (A.z, A.w, B.x, B.y)
        acc.x = fmaf(A.z,  dv[1].x, acc.x);
        acc.y = fmaf(A.w,  dv[1].y, acc.y);
        acc.z = fmaf(Bv.x, dv[1].z, acc.z);
        acc.w = fmaf(Bv.y, dv[1].w, acc.w);
        // t=2: B
        acc.x = fmaf(Bv.x, dv[2].x, acc.x);
        acc.y = fmaf(Bv.y, dv[2].y, acc.y);
        acc.z = fmaf(Bv.z, dv[2].z, acc.z);
        acc.w = fmaf(Bv.w, dv[2].w, acc.w);

        #define ACC(T, X)                                   \
            acc.x = fmaf((X).x, dv[T].x, acc.x);            \
            acc.y = fmaf((X).y, dv[T].y, acc.y);            \
            acc.z = fmaf((X).z, dv[T].z, acc.z);            \
            acc.w = fmaf((X).w, dv[T].w, acc.w);

        ACC(3, X3) ACC(4, X4) ACC(5, X5) ACC(6, X6) ACC(7, X7)
        #undef ACC

        o4[(size_t)b * SQ + oq] = acc;
    }
}

// ---------------------------------------------------------------------------
// Kernel 2: t = 8..15 (shifts 256..32768, all quad-aligned). out += partial.
// ---------------------------------------------------------------------------
__global__ __launch_bounds__(TPB, 3)
void fhe_bsgs_hi(const float* __restrict__ x,
                 const float* __restrict__ diag,
                 float* __restrict__ out)
{
    const int s  = blockIdx.x * (TPB * 4) + threadIdx.x * 4;
    const int s2 = s ^ 32768;
    const int b0 = blockIdx.y * BPC;

    const float4* __restrict__ x4 = reinterpret_cast<const float4*>(x);
    const float4* __restrict__ d4 = reinterpret_cast<const float4*>(diag);
    float4* __restrict__ o4 = reinterpret_cast<float4*>(out);

    const unsigned q2 = (unsigned)s2 >> 2;

    float4 dv[8];
    #pragma unroll
    for (int t = 0; t < 8; t++)
        dv[t] = d4[(t + 8) * SQ + q2];

    unsigned qt[8];
    #pragma unroll
    for (int t = 0; t < 8; t++)
        qt[t] = ((unsigned)(s2 + (256 << t)) & SMASK) >> 2;

    const unsigned oq = (unsigned)s >> 2;

    #pragma unroll
    for (int i = 0; i < BPC; i++) {
        const int b = b0 + i;
        const float4* __restrict__ xr = x4 + (size_t)b * SQ;

        const float4 X0 = xr[qt[0]];
        const float4 X1 = xr[qt[1]];
        const float4 X2 = xr[qt[2]];
        const float4 X3 = xr[qt[3]];
        const float4 X4 = xr[qt[4]];
        const float4 X5 = xr[qt[5]];
        const float4 X6 = xr[qt[6]];
        const float4 X7 = xr[qt[7]];

        float4 acc = o4[(size_t)b * SQ + oq];   // partial from kernel 1

        #define ACC(T, X)                                   \
            acc.x = fmaf((X).x, dv[T].x, acc.x);            \
            acc.y = fmaf((X).y, dv[T].y, acc.y);            \
            acc.z = fmaf((X).z, dv[T].z, acc.z);            \
            acc.w = fmaf((X).w, dv[T].w, acc.w);

        ACC(0, X0) ACC(1, X1) ACC(2, X2) ACC(3, X3)
        ACC(4, X4) ACC(5, X5) ACC(6, X6) ACC(7, X7)
        #undef ACC

        o4[(size_t)b * SQ + oq] = acc;
    }
}

extern "C" void kernel_launch(void* const* d_in, const int* in_sizes, int n_in,
                              void* d_out, int out_size)
{
    const float* x    = (const float*)d_in[0];
    const float* diag = (const float*)d_in[1];
    float* out = (float*)d_out;

    dim3 grid(SLOTS / (TPB * 4), BATCH / BPC);  // 64 x 8 = 512 CTAs each
    fhe_bsgs_lo<<<grid, TPB>>>(x, diag, out);
    fhe_bsgs_hi<<<grid, TPB>>>(x, diag, out);
}

// round 4
// speedup vs baseline: 1.3205x; 1.3205x over previous
#include <cuda_runtime.h>
#include <cstdint>

// FHE BSGS rotate/mul/accumulate. Fixed shapes: x[64,65536] f32, diag[16,65536] f32,
// stride=1, reps=1 -> out[b,s] = sum_t x[b,(s^32768 + 2^t) & 65535] * diag[t, s^32768].
#define SLOTS   65536
#define SQ      (SLOTS / 4)       // 16384 quads per row
#define QM      (SQ - 1)
#define NT      16
#define BATCH   64
#define BPC     8                 // batches per CTA
#define TPB     256               // 1 output quad per thread -> 1024-slot tile
#define UQ      1792              // union quads per batch: 768 near + 4*256 far
#define SMEM_BYTES (2 * UQ * 16)  // double buffer, 57344 B

__device__ __forceinline__ void cpasync16(uint32_t saddr, const float4* g) {
    asm volatile("cp.async.cg.shared.global [%0], [%1], 16;\n" :: "r"(saddr), "l"(g));
}
__device__ __forceinline__ void cp_commit() {
    asm volatile("cp.async.commit_group;\n");
}
__device__ __forceinline__ void cp_wait1() {
    asm volatile("cp.async.wait_group 1;\n");
}
__device__ __forceinline__ void cp_wait0() {
    asm volatile("cp.async.wait_group 0;\n");
}

__global__ __launch_bounds__(TPB, 2)
void fhe_bsgs_smem(const float* __restrict__ x,
                   const float* __restrict__ diag,
                   float* __restrict__ out)
{
    extern __shared__ float4 sbuf[];   // [2][UQ]

    const int tid = threadIdx.x;
    const int Sq  = blockIdx.x * TPB;           // output quad base
    const int Tq  = (Sq * 4 ^ 32768) >> 2;      // rolled (s2-space) quad base
    const int b0  = blockIdx.y * BPC;

    const float4* __restrict__ x4 = reinterpret_cast<const float4*>(x);
    const float4* __restrict__ d4 = reinterpret_cast<const float4*>(diag);
    float4* __restrict__ o4 = reinterpret_cast<float4*>(out);

    // Batch-invariant diag quads for this thread's slot quad (q2 = Tq + tid < SQ).
    const int q2 = Tq + tid;
    float4 dv[NT];
    #pragma unroll
    for (int t = 0; t < NT; t++)
        dv[t] = d4[t * SQ + q2];

    const uint32_t sb0 = (uint32_t)__cvta_generic_to_shared(sbuf);

    // Stage union for batch b into buffer `buf`.
    // Layout (quads): [0,768) near = x quads (Tq+k)&QM, covers shifts 1..2048 (+B quad);
    //                 [768+256g, +256) far g = x quads (Tq + (1024<<g) + tid)&QM, g=0..3.
    auto stage = [&](int buf, int b) {
        const float4* __restrict__ xb = x4 + (size_t)b * SQ;
        const uint32_t sb = sb0 + (uint32_t)buf * (UQ * 16);
        #pragma unroll
        for (int r = 0; r < 3; r++) {
            const int k = tid + 256 * r;
            cpasync16(sb + k * 16, xb + ((Tq + k) & QM));
        }
        #pragma unroll
        for (int g = 0; g < 4; g++) {
            const int k = 768 + 256 * g + tid;
            cpasync16(sb + k * 16, xb + ((Tq + (1024 << g) + tid) & QM));
        }
        cp_commit();
    };

    stage(0, b0);

    #pragma unroll 1
    for (int i = 0; i < BPC; i++) {
        if (i + 1 < BPC) {
            stage((i + 1) & 1, b0 + i + 1);   // prefetch next batch (other buffer)
            cp_wait1();                        // current batch's group complete
        } else {
            cp_wait0();
        }
        __syncthreads();

        const float4* __restrict__ buf = sbuf + (i & 1) * UQ;

        const float4 A  = buf[tid];
        const float4 Bv = buf[tid + 1];

        float4 acc;
        // t=0 (shift 1): (A.y, A.z, A.w, B.x)
        acc.x = A.y  * dv[0].x;
        acc.y = A.z  * dv[0].y;
        acc.z = A.w  * dv[0].z;
        acc.w = Bv.x * dv[0].w;
        // t=1 (shift 2): (A.z, A.w, B.x, B.y)
        acc.x = fmaf(A.z,  dv[1].x, acc.x);
        acc.y = fmaf(A.w,  dv[1].y, acc.y);
        acc.z = fmaf(Bv.x, dv[1].z, acc.z);
        acc.w = fmaf(Bv.y, dv[1].w, acc.w);
        // t=2 (shift 4): quad tid+1 = Bv
        acc.x = fmaf(Bv.x, dv[2].x, acc.x);
        acc.y = fmaf(Bv.y, dv[2].y, acc.y);
        acc.z = fmaf(Bv.z, dv[2].z, acc.z);
        acc.w = fmaf(Bv.w, dv[2].w, acc.w);

        #define ACCQ(T, IDX) do {                           \
            const float4 X = buf[(IDX)];                    \
            acc.x = fmaf(X.x, dv[T].x, acc.x);              \
            acc.y = fmaf(X.y, dv[T].y, acc.y);              \
            acc.z = fmaf(X.z, dv[T].z, acc.z);              \
            acc.w = fmaf(X.w, dv[T].w, acc.w);              \
        } while (0)

        // t=3..11 (shifts 8..2048): near block, quad tid + 2^(t-2)
        ACCQ(3,  tid + 2);
        ACCQ(4,  tid + 4);
        ACCQ(5,  tid + 8);
        ACCQ(6,  tid + 16);
        ACCQ(7,  tid + 32);
        ACCQ(8,  tid + 64);
        ACCQ(9,  tid + 128);
        ACCQ(10, tid + 256);
        ACCQ(11, tid + 512);
        // t=12..15 (shifts 4096..32768): far blocks
        ACCQ(12, 768 + 0   + tid);
        ACCQ(13, 768 + 256 + tid);
        ACCQ(14, 768 + 512 + tid);
        ACCQ(15, 768 + 768 + tid);
        #undef ACCQ

        o4[(size_t)(b0 + i) * SQ + Sq + tid] = acc;

        __syncthreads();   // compute done before this buffer is restaged
    }
}

extern "C" void kernel_launch(void* const* d_in, const int* in_sizes, int n_in,
                              void* d_out, int out_size)
{
    const float* x    = (const float*)d_in[0];
    const float* diag = (const float*)d_in[1];
    float* out = (float*)d_out;

    static bool attr_set = false;
    if (!attr_set) {
        cudaFuncSetAttribute(fhe_bsgs_smem,
                             cudaFuncAttributeMaxDynamicSharedMemorySize, SMEM_BYTES);
        attr_set = true;
    }

    dim3 grid(SLOTS / (TPB * 4), BATCH / BPC);   // (64, 8) = 512 CTAs
    fhe_bsgs_smem<<<grid, TPB, SMEM_BYTES>>>(x, diag, out);
}

// round 5
// speedup vs baseline: 1.3227x; 1.0017x over previous
#include <cuda_runtime.h>
#include <cstdint>

// FHE BSGS rotate/mul/accumulate. Fixed shapes: x[64,65536] f32, diag[16,65536] f32,
// stride=1, reps=1 -> out[b,s] = sum_t x[b,(s^32768 + 2^t) & 65535] * diag[t, s^32768].
#define SLOTS   65536
#define SQ      (SLOTS / 4)       // 16384 quads per row
#define QM      (SQ - 1)
#define NT      16
#define BATCH   64
#define BPC     8                 // batches per CTA
#define TPB     256               // 1 output quad per thread -> 1024-slot tile
#define NEARQ   768               // near-union quads (shifts 1..2048 + B quad)
#define SMEM_BYTES (2 * NEARQ * 16)   // double buffer, 24576 B (fits default 48KB)

__device__ __forceinline__ void cpasync16(uint32_t saddr, const float4* g) {
    asm volatile("cp.async.cg.shared.global [%0], [%1], 16;\n" :: "r"(saddr), "l"(g));
}
__device__ __forceinline__ void cp_commit() { asm volatile("cp.async.commit_group;\n"); }
__device__ __forceinline__ void cp_wait1()  { asm volatile("cp.async.wait_group 1;\n"); }
__device__ __forceinline__ void cp_wait0()  { asm volatile("cp.async.wait_group 0;\n"); }

__global__ __launch_bounds__(TPB, 2)
void fhe_bsgs_hybrid(const float* __restrict__ x,
                     const float* __restrict__ diag,
                     float* __restrict__ out)
{
    extern __shared__ float4 sbuf[];   // [2][NEARQ]

    const int tid = threadIdx.x;
    const int Sq  = blockIdx.x * TPB;          // output quad base
    const int Tq  = (Sq * 4 ^ 32768) >> 2;     // rolled (s2-space) quad base
    const int b0  = blockIdx.y * BPC;

    const float4* __restrict__ x4 = reinterpret_cast<const float4*>(x);
    const float4* __restrict__ d4 = reinterpret_cast<const float4*>(diag);
    float4* __restrict__ o4 = reinterpret_cast<float4*>(out);

    // Batch-invariant diag quads for this thread's slot quad.
    const int q2 = Tq + tid;
    float4 dv[NT];
    #pragma unroll
    for (int t = 0; t < NT; t++)
        dv[t] = d4[t * SQ + q2];

    const uint32_t sb0 = (uint32_t)__cvta_generic_to_shared(sbuf);

    // Far quad indices (shifts 4096,8192,16384,32768 -> 1024..8192 quads), coalesced.
    unsigned qf[4];
    #pragma unroll
    for (int g = 0; g < 4; g++)
        qf[g] = (unsigned)(Tq + (1024 << g) + tid) & QM;

    // Stage near union [Tq, Tq+768) for batch b into buffer `buf`.
    auto stage_near = [&](int buf, int b) {
        const float4* __restrict__ xb = x4 + (size_t)b * SQ;
        const uint32_t sb = sb0 + (uint32_t)buf * (NEARQ * 16);
        #pragma unroll
        for (int r = 0; r < 3; r++) {
            const int k = tid + 256 * r;
            cpasync16(sb + k * 16, xb + ((Tq + k) & QM));
        }
        cp_commit();
    };

    // Prime the pipeline: near(batch 0) staging + far(batch 0) register loads.
    stage_near(0, b0);
    float4 F0, F1, F2, F3;
    {
        const float4* __restrict__ xb = x4 + (size_t)b0 * SQ;
        F0 = xb[qf[0]]; F1 = xb[qf[1]]; F2 = xb[qf[2]]; F3 = xb[qf[3]];
    }

    #pragma unroll 1
    for (int i = 0; i < BPC; i++) {
        if (i + 1 < BPC) {
            stage_near((i + 1) & 1, b0 + i + 1);  // prefetch next near block
            cp_wait1();                            // current batch's group complete
        } else {
            cp_wait0();
        }
        __syncthreads();

        // Issue next batch's far LDGs now; awaited only next iteration.
        float4 G0, G1, G2, G3;
        if (i + 1 < BPC) {
            const float4* __restrict__ xn = x4 + (size_t)(b0 + i + 1) * SQ;
            G0 = xn[qf[0]]; G1 = xn[qf[1]]; G2 = xn[qf[2]]; G3 = xn[qf[3]];
        }

        const float4* __restrict__ buf = sbuf + (i & 1) * NEARQ;

        const float4 A  = buf[tid];
        const float4 Bv = buf[tid + 1];

        // Chain 1: t = 0..7
        float4 a1;
        a1.x = A.y  * dv[0].x;              // t=0: (A.y,A.z,A.w,B.x)
        a1.y = A.z  * dv[0].y;
        a1.z = A.w  * dv[0].z;
        a1.w = Bv.x * dv[0].w;
        a1.x = fmaf(A.z,  dv[1].x, a1.x);   // t=1: (A.z,A.w,B.x,B.y)
        a1.y = fmaf(A.w,  dv[1].y, a1.y);
        a1.z = fmaf(Bv.x, dv[1].z, a1.z);
        a1.w = fmaf(Bv.y, dv[1].w, a1.w);
        a1.x = fmaf(Bv.x, dv[2].x, a1.x);   // t=2: B
        a1.y = fmaf(Bv.y, dv[2].y, a1.y);
        a1.z = fmaf(Bv.z, dv[2].z, a1.z);
        a1.w = fmaf(Bv.w, dv[2].w, a1.w);

        #define ACCQ(ACCV, T, IDX) do {                     \
            const float4 X = buf[(IDX)];                    \
            ACCV.x = fmaf(X.x, dv[T].x, ACCV.x);            \
            ACCV.y = fmaf(X.y, dv[T].y, ACCV.y);            \
            ACCV.z = fmaf(X.z, dv[T].z, ACCV.z);            \
            ACCV.w = fmaf(X.w, dv[T].w, ACCV.w);            \
        } while (0)

        ACCQ(a1, 3, tid + 2);
        ACCQ(a1, 4, tid + 4);
        ACCQ(a1, 5, tid + 8);
        ACCQ(a1, 6, tid + 16);
        ACCQ(a1, 7, tid + 32);

        // Chain 2: t = 8..15
        float4 a2;
        {
            const float4 X = buf[tid + 64];   // t=8
            a2.x = X.x * dv[8].x;
            a2.y = X.y * dv[8].y;
            a2.z = X.z * dv[8].z;
            a2.w = X.w * dv[8].w;
        }
        ACCQ(a2,  9, tid + 128);
        ACCQ(a2, 10, tid + 256);
        ACCQ(a2, 11, tid + 512);
        #undef ACCQ

        // Far shifts from prefetched registers (t=12..15)
        a2.x = fmaf(F0.x, dv[12].x, a2.x);
        a2.y = fmaf(F0.y, dv[12].y, a2.y);
        a2.z = fmaf(F0.z, dv[12].z, a2.z);
        a2.w = fmaf(F0.w, dv[12].w, a2.w);
        a2.x = fmaf(F1.x, dv[13].x, a2.x);
        a2.y = fmaf(F1.y, dv[13].y, a2.y);
        a2.z = fmaf(F1.z, dv[13].z, a2.z);
        a2.w = fmaf(F1.w, dv[13].w, a2.w);
        a2.x = fmaf(F2.x, dv[14].x, a2.x);
        a2.y = fmaf(F2.y, dv[14].y, a2.y);
        a2.z = fmaf(F2.z, dv[14].z, a2.z);
        a2.w = fmaf(F2.w, dv[14].w, a2.w);
        a2.x = fmaf(F3.x, dv[15].x, a2.x);
        a2.y = fmaf(F3.y, dv[15].y, a2.y);
        a2.z = fmaf(F3.z, dv[15].z, a2.z);
        a2.w = fmaf(F3.w, dv[15].w, a2.w);

        float4 acc;
        acc.x = a1.x + a2.x;
        acc.y = a1.y + a2.y;
        acc.z = a1.z + a2.z;
        acc.w = a1.w + a2.w;

        o4[(size_t)(b0 + i) * SQ + Sq + tid] = acc;

        F0 = G0; F1 = G1; F2 = G2; F3 = G3;

        __syncthreads();   // compute done before this buffer is restaged
    }
}

extern "C" void kernel_launch(void* const* d_in, const int* in_sizes, int n_in,
                              void* d_out, int out_size)
{
    const float* x    = (const float*)d_in[0];
    const float* diag = (const float*)d_in[1];
    float* out = (float*)d_out;

    dim3 grid(SLOTS / (TPB * 4), BATCH / BPC);   // (64, 8) = 512 CTAs
    fhe_bsgs_hybrid<<<grid, TPB, SMEM_BYTES>>>(x, diag, out);
}

// round 6
// speedup vs baseline: 1.3384x; 1.0118x over previous
#include <cuda_runtime.h>
#include <cstdint>

// FHE BSGS rotate/mul/accumulate. Fixed shapes: x[64,65536] f32, diag[16,65536] f32,
// stride=1, reps=1 -> out[b,s] = sum_t x[b,(s^32768 + 2^t) & 65535] * diag[t, s^32768].
#define SLOTS   65536
#define SQ      (SLOTS / 4)       // 16384 quads per row
#define QM      (SQ - 1)
#define BATCH   64
#define BPC     8                 // batches per CTA
#define TPB     256               // 1 output quad per thread -> 1024-slot tile
#define NEARQ   768               // near-union quads (shifts 1..2048 + B quad)
#define NBUF    3                 // triple buffer -> single barrier per iteration
#define SMEM_BYTES (NBUF * NEARQ * 16)   // 36864 B

typedef unsigned long long u64;

__device__ __forceinline__ void cpasync16(uint32_t saddr, const float4* g) {
    asm volatile("cp.async.cg.shared.global [%0], [%1], 16;\n" :: "r"(saddr), "l"(g));
}
__device__ __forceinline__ void cp_commit() { asm volatile("cp.async.commit_group;\n"); }
__device__ __forceinline__ void cp_wait1()  { asm volatile("cp.async.wait_group 1;\n"); }
__device__ __forceinline__ void cp_wait0()  { asm volatile("cp.async.wait_group 0;\n"); }

// Packed dual-fp32 FMA (Blackwell f32x2 pipe; not emitted from C++).
__device__ __forceinline__ u64 fma2(u64 x, u64 d, u64 a) {
    u64 r;
    asm("fma.rn.f32x2 %0, %1, %2, %3;" : "=l"(r) : "l"(x), "l"(d), "l"(a));
    return r;
}
__device__ __forceinline__ u64 mul2(u64 x, u64 d) {
    u64 r;
    asm("mul.rn.f32x2 %0, %1, %2;" : "=l"(r) : "l"(x), "l"(d));
    return r;
}
__device__ __forceinline__ u64 add2(u64 x, u64 y) {
    u64 r;
    asm("add.rn.f32x2 %0, %1, %2;" : "=l"(r) : "l"(x), "l"(y));
    return r;
}
__device__ __forceinline__ u64 pack2(float lo, float hi) {
    u64 r;
    asm("mov.b64 %0, {%1, %2};" : "=l"(r) : "f"(lo), "f"(hi));
    return r;
}

__global__ __launch_bounds__(TPB, 2)
void fhe_bsgs_p2(const float* __restrict__ x,
                 const float* __restrict__ diag,
                 float* __restrict__ out)
{
    extern __shared__ float4 sbuf[];   // [NBUF][NEARQ]

    const int tid = threadIdx.x;
    const int Sq  = blockIdx.x * TPB;          // output quad base
    const int Tq  = (Sq * 4 ^ 32768) >> 2;     // rolled (s2-space) quad base
    const int b0  = blockIdx.y * BPC;

    const float4* __restrict__ x4 = reinterpret_cast<const float4*>(x);
    float4* __restrict__ o4 = reinterpret_cast<float4*>(out);

    // Batch-invariant diag quads. t=0..2 as float4 (scalar windows), t=3..15 packed.
    const int q2 = Tq + tid;
    float4 dvs[3];
    #pragma unroll
    for (int t = 0; t < 3; t++)
        dvs[t] = reinterpret_cast<const float4*>(diag)[t * SQ + q2];
    ulonglong2 dvp[13];
    #pragma unroll
    for (int t = 3; t < 16; t++)
        dvp[t - 3] = reinterpret_cast<const ulonglong2*>(diag)[t * SQ + q2];

    const uint32_t sb0 = (uint32_t)__cvta_generic_to_shared(sbuf);

    // Far quad indices (shifts 4096..32768 -> 1024..8192 quads), coalesced LDG.
    unsigned qf[4];
    #pragma unroll
    for (int g = 0; g < 4; g++)
        qf[g] = (unsigned)(Tq + (1024 << g) + tid) & QM;

    auto stage_near = [&](int buf, int b) {
        const float4* __restrict__ xb = x4 + (size_t)b * SQ;
        const uint32_t sb = sb0 + (uint32_t)buf * (NEARQ * 16);
        #pragma unroll
        for (int r = 0; r < 3; r++) {
            const int k = tid + 256 * r;
            cpasync16(sb + k * 16, xb + ((Tq + k) & QM));
        }
        cp_commit();
    };

    // Prime: stage batch 0; far loads for batch 0.
    stage_near(0, b0);
    ulonglong2 F[4];
    {
        const ulonglong2* __restrict__ xb =
            reinterpret_cast<const ulonglong2*>(x) + (size_t)b0 * SQ;
        #pragma unroll
        for (int g = 0; g < 4; g++) F[g] = xb[qf[g]];
    }

    #pragma unroll 1
    for (int i = 0; i < BPC; i++) {
        if (i + 1 < BPC) {
            stage_near((i + 1) % NBUF, b0 + i + 1);
            cp_wait1();                 // group(i) complete; group(i+1) in flight
        } else {
            cp_wait0();
        }

        // Next batch's far LDGs: issued now, consumed next iteration.
        ulonglong2 G[4];
        if (i + 1 < BPC) {
            const ulonglong2* __restrict__ xn =
                reinterpret_cast<const ulonglong2*>(x) + (size_t)(b0 + i + 1) * SQ;
            #pragma unroll
            for (int g = 0; g < 4; g++) G[g] = xn[qf[g]];
        }

        __syncthreads();                // single barrier per iteration (triple buffer)

        const float4* __restrict__ buf = sbuf + (i % NBUF) * NEARQ;
        const ulonglong2* __restrict__ buf64 = reinterpret_cast<const ulonglong2*>(buf);

        const float4 A  = buf[tid];
        const float4 Bv = buf[tid + 1];

        // t=0..2 scalar (misaligned windows), accumulated per component.
        float s0, s1, s2, s3;
        s0 = A.y  * dvs[0].x;                 // t=0: (A.y,A.z,A.w,B.x)
        s1 = A.z  * dvs[0].y;
        s2 = A.w  * dvs[0].z;
        s3 = Bv.x * dvs[0].w;
        s0 = fmaf(A.z,  dvs[1].x, s0);        // t=1: (A.z,A.w,B.x,B.y)
        s1 = fmaf(A.w,  dvs[1].y, s1);
        s2 = fmaf(Bv.x, dvs[1].z, s2);
        s3 = fmaf(Bv.y, dvs[1].w, s3);
        s0 = fmaf(Bv.x, dvs[2].x, s0);        // t=2: B
        s1 = fmaf(Bv.y, dvs[2].y, s1);
        s2 = fmaf(Bv.z, dvs[2].z, s2);
        s3 = fmaf(Bv.w, dvs[2].w, s3);

        // Chain 1 (t=0..7): packed, seeded from scalar partials.
        u64 a1lo = pack2(s0, s1);
        u64 a1hi = pack2(s2, s3);

        #define ACCP(CLO, CHI, T, IDX) do {                 \
            const ulonglong2 X = buf64[(IDX)];              \
            CLO = fma2(X.x, dvp[(T) - 3].x, CLO);           \
            CHI = fma2(X.y, dvp[(T) - 3].y, CHI);           \
        } while (0)

        ACCP(a1lo, a1hi, 3, tid + 2);
        ACCP(a1lo, a1hi, 4, tid + 4);
        ACCP(a1lo, a1hi, 5, tid + 8);
        ACCP(a1lo, a1hi, 6, tid + 16);
        ACCP(a1lo, a1hi, 7, tid + 32);

        // Chain 2 (t=8..15): packed.
        u64 a2lo, a2hi;
        {
            const ulonglong2 X = buf64[tid + 64];           // t=8
            a2lo = mul2(X.x, dvp[5].x);
            a2hi = mul2(X.y, dvp[5].y);
        }
        ACCP(a2lo, a2hi,  9, tid + 128);
        ACCP(a2lo, a2hi, 10, tid + 256);
        ACCP(a2lo, a2hi, 11, tid + 512);
        #undef ACCP

        // Far shifts t=12..15 from prefetched registers.
        #pragma unroll
        for (int g = 0; g < 4; g++) {
            a2lo = fma2(F[g].x, dvp[9 + g].x, a2lo);
            a2hi = fma2(F[g].y, dvp[9 + g].y, a2hi);
        }

        ulonglong2 acc;
        acc.x = add2(a1lo, a2lo);
        acc.y = add2(a1hi, a2hi);

        reinterpret_cast<ulonglong2*>(o4)[(size_t)(b0 + i) * SQ + Sq + tid] = acc;

        #pragma unroll
        for (int g = 0; g < 4; g++) F[g] = G[g];
    }
}

extern "C" void kernel_launch(void* const* d_in, const int* in_sizes, int n_in,
                              void* d_out, int out_size)
{
    const float* x    = (const float*)d_in[0];
    const float* diag = (const float*)d_in[1];
    float* out = (float*)d_out;

    dim3 grid(SLOTS / (TPB * 4), BATCH / BPC);   // (64, 8) = 512 CTAs
    fhe_bsgs_p2<<<grid, TPB, SMEM_BYTES>>>(x, diag, out);
}